// round 1
// baseline (speedup 1.0000x reference)
#include <cuda_runtime.h>
#include <cuda_fp16.h>
#include <mma.h>

using namespace nvcuda;

#define T_TOKENS 4096
#define DDIM 1024
#define MDIM 2048
#define NEXP 8
#define ROWS_PAD 9216      // 72 tiles * 128 rows (worst case 64 + 7 ragged + slack)
#define MAX_TILES 72

// ---------------- device scratch (no allocations allowed) ----------------
__device__ __half g_Wg[NEXP * DDIM * MDIM];   // 33.5 MB fp16 gate weights
__device__ __half g_Wu[NEXP * DDIM * MDIM];   // 33.5 MB fp16 up weights
__device__ __half g_Wo[NEXP * MDIM * DDIM];   // 33.5 MB fp16 out weights
__device__ __half g_X[ROWS_PAD * DDIM];       // gathered activations (fp16)
__device__ __half g_H[ROWS_PAD * MDIM];       // hidden = silu(g)*u (fp16)
__device__ float  g_Y[ROWS_PAD * DDIM];       // expert outputs (fp32)
__device__ int    g_counts[NEXP];
__device__ int    g_offsets[NEXP + 1];
__device__ int    g_tile_expert[MAX_TILES];
__device__ int    g_row_tok[ROWS_PAD];
__device__ int    g_tok_e[T_TOKENS * 2];
__device__ int    g_tok_slot[T_TOKENS * 2];
__device__ float  g_tok_w[T_TOKENS * 2];

// ---------------- init ----------------
__global__ void init_kernel() {
    int i = blockIdx.x * blockDim.x + threadIdx.x;
    if (i < NEXP) g_counts[i] = 0;
    if (i < ROWS_PAD) g_row_tok[i] = -1;
}

// ---------------- fp32 -> fp16 weight conversion ----------------
__global__ void convert_kernel(const float* __restrict__ wg,
                               const float* __restrict__ wu,
                               const float* __restrict__ wo) {
    int i = blockIdx.x * blockDim.x + threadIdx.x;   // one float4 group
    const int n4 = NEXP * DDIM * MDIM / 4;           // 4,194,304
    if (i >= n4) return;
    float4 a = reinterpret_cast<const float4*>(wg)[i];
    float4 b = reinterpret_cast<const float4*>(wu)[i];
    float4 c = reinterpret_cast<const float4*>(wo)[i];
    __half2* pg = reinterpret_cast<__half2*>(g_Wg);
    __half2* pu = reinterpret_cast<__half2*>(g_Wu);
    __half2* po = reinterpret_cast<__half2*>(g_Wo);
    pg[2 * i]     = __floats2half2_rn(a.x, a.y);
    pg[2 * i + 1] = __floats2half2_rn(a.z, a.w);
    pu[2 * i]     = __floats2half2_rn(b.x, b.y);
    pu[2 * i + 1] = __floats2half2_rn(b.z, b.w);
    po[2 * i]     = __floats2half2_rn(c.x, c.y);
    po[2 * i + 1] = __floats2half2_rn(c.z, c.w);
}

// ---------------- router: logits -> softmax -> top2 -> renorm ----------------
__global__ void router_kernel(const float* __restrict__ residual,
                              const float* __restrict__ Wr) {
    int t = blockIdx.x;
    __shared__ float xs[DDIM];
    __shared__ float logits[NEXP];
    int tid = threadIdx.x;   // 256 threads = 8 warps
    const float* x = residual + (size_t)t * DDIM;
    for (int i = tid; i < DDIM; i += 256) xs[i] = x[i];
    __syncthreads();
    int w = tid >> 5, lane = tid & 31;
    float s = 0.f;
    for (int i = lane; i < DDIM; i += 32) s += xs[i] * Wr[i * NEXP + w];
    #pragma unroll
    for (int o = 16; o > 0; o >>= 1) s += __shfl_xor_sync(0xffffffff, s, o);
    if (lane == 0) logits[w] = s;
    __syncthreads();
    if (tid == 0) {
        float mx = logits[0];
        #pragma unroll
        for (int e = 1; e < NEXP; e++) mx = fmaxf(mx, logits[e]);
        float p[NEXP]; float sum = 0.f;
        #pragma unroll
        for (int e = 0; e < NEXP; e++) { p[e] = expf(logits[e] - mx); sum += p[e]; }
        #pragma unroll
        for (int e = 0; e < NEXP; e++) p[e] /= sum;
        int i1 = 0;
        #pragma unroll
        for (int e = 1; e < NEXP; e++) if (p[e] > p[i1]) i1 = e;  // ties: lowest idx
        int i2 = -1;
        #pragma unroll
        for (int e = 0; e < NEXP; e++) {
            if (e == i1) continue;
            if (i2 < 0 || p[e] > p[i2]) i2 = e;
        }
        float w1 = p[i1], w2 = p[i2];
        float inv = 1.f / (w1 + w2 + 1e-8f);
        w1 *= inv; w2 *= inv;
        int s1 = atomicAdd(&g_counts[i1], 1);
        int s2 = atomicAdd(&g_counts[i2], 1);
        g_tok_e[2 * t] = i1;     g_tok_e[2 * t + 1] = i2;
        g_tok_slot[2 * t] = s1;  g_tok_slot[2 * t + 1] = s2;
        g_tok_w[2 * t] = w1;     g_tok_w[2 * t + 1] = w2;
    }
}

// ---------------- offsets + tile map (1 thread; 8 experts) ----------------
__global__ void scan_kernel() {
    int off = 0, tile = 0;
    for (int e = 0; e < NEXP; e++) {
        g_offsets[e] = off;
        int nt = (g_counts[e] + 127) / 128;
        for (int k = 0; k < nt; k++) g_tile_expert[tile++] = e;
        off += nt * 128;
    }
    g_offsets[NEXP] = off;
    for (; tile < MAX_TILES; tile++) g_tile_expert[tile] = -1;
}

__global__ void scatter_kernel() {
    int i = blockIdx.x * blockDim.x + threadIdx.x;
    if (i >= T_TOKENS * 2) return;
    int e = g_tok_e[i];
    int row = g_offsets[e] + g_tok_slot[i];
    g_row_tok[row] = i >> 1;
}

// ---------------- gather token rows -> fp16 X ----------------
__global__ void gather_kernel(const float* __restrict__ residual) {
    int row = blockIdx.x;
    int c = threadIdx.x * 8;   // 128 threads * 8 = 1024 cols
    int tok = g_row_tok[row];
    __half2 h[4];
    if (tok < 0) {
        __half2 z = __half2half2(__float2half(0.f));
        h[0] = z; h[1] = z; h[2] = z; h[3] = z;
    } else {
        const float4* src = reinterpret_cast<const float4*>(residual + (size_t)tok * DDIM + c);
        float4 a = src[0], b = src[1];
        h[0] = __floats2half2_rn(a.x, a.y); h[1] = __floats2half2_rn(a.z, a.w);
        h[2] = __floats2half2_rn(b.x, b.y); h[3] = __floats2half2_rn(b.z, b.w);
    }
    *reinterpret_cast<uint4*>(g_X + row * DDIM + c) = *reinterpret_cast<uint4*>(h);
}

// ---------------- GEMM1: fused gate+up, 128x64 tile, BK=32, wmma ----------------
__global__ void __launch_bounds__(256) gemm1_kernel(const float* __restrict__ bg,
                                                    const float* __restrict__ bu) {
    int e = g_tile_expert[blockIdx.x];
    if (e < 0) return;
    int row0 = blockIdx.x * 128;
    int n0 = blockIdx.y * 64;

    __shared__ __half As[128][40];
    __shared__ __half Bgs[32][72];
    __shared__ __half Bus[32][72];
    __shared__ float patchG[8][16][20];
    __shared__ float patchU[8][16][20];

    int tid = threadIdx.x;
    int w = tid >> 5, lane = tid & 31;
    int wm = w >> 1, wn = w & 1;   // 4x2 warp grid, each warp 32x32

    const __half* Wgb = g_Wg + (size_t)e * DDIM * MDIM;
    const __half* Wub = g_Wu + (size_t)e * DDIM * MDIM;

    wmma::fragment<wmma::accumulator, 16, 16, 16, float> accG[2][2], accU[2][2];
    #pragma unroll
    for (int i = 0; i < 2; i++)
        #pragma unroll
        for (int j = 0; j < 2; j++) {
            wmma::fill_fragment(accG[i][j], 0.f);
            wmma::fill_fragment(accU[i][j], 0.f);
        }

    for (int kt = 0; kt < DDIM / 32; kt++) {
        int k0 = kt * 32;
        __syncthreads();
        // A: 128x32 halfs = 512 uint4; 2 per thread
        #pragma unroll
        for (int v = tid; v < 512; v += 256) {
            int r = v >> 2, cseg = (v & 3) * 8;
            *reinterpret_cast<uint4*>(&As[r][cseg]) =
                *reinterpret_cast<const uint4*>(&g_X[(row0 + r) * DDIM + k0 + cseg]);
        }
        // B: 32x64 halfs each = 256 uint4; 1 per thread per matrix
        {
            int r = tid >> 3, cseg = (tid & 7) * 8;
            *reinterpret_cast<uint4*>(&Bgs[r][cseg]) =
                *reinterpret_cast<const uint4*>(&Wgb[(k0 + r) * MDIM + n0 + cseg]);
            *reinterpret_cast<uint4*>(&Bus[r][cseg]) =
                *reinterpret_cast<const uint4*>(&Wub[(k0 + r) * MDIM + n0 + cseg]);
        }
        __syncthreads();

        #pragma unroll
        for (int kk = 0; kk < 32; kk += 16) {
            wmma::fragment<wmma::matrix_a, 16, 16, 16, __half, wmma::row_major> a[2];
            wmma::fragment<wmma::matrix_b, 16, 16, 16, __half, wmma::row_major> bgf[2], buf[2];
            #pragma unroll
            for (int im = 0; im < 2; im++)
                wmma::load_matrix_sync(a[im], &As[wm * 32 + im * 16][kk], 40);
            #pragma unroll
            for (int in = 0; in < 2; in++) {
                wmma::load_matrix_sync(bgf[in], &Bgs[kk][wn * 32 + in * 16], 72);
                wmma::load_matrix_sync(buf[in], &Bus[kk][wn * 32 + in * 16], 72);
            }
            #pragma unroll
            for (int im = 0; im < 2; im++)
                #pragma unroll
                for (int in = 0; in < 2; in++) {
                    wmma::mma_sync(accG[im][in], a[im], bgf[in], accG[im][in]);
                    wmma::mma_sync(accU[im][in], a[im], buf[in], accU[im][in]);
                }
        }
    }

    // epilogue: h = silu(g + bg) * (u + bu), write fp16 H
    #pragma unroll
    for (int im = 0; im < 2; im++)
        #pragma unroll
        for (int in = 0; in < 2; in++) {
            wmma::store_matrix_sync(&patchG[w][0][0], accG[im][in], 20, wmma::mem_row_major);
            wmma::store_matrix_sync(&patchU[w][0][0], accU[im][in], 20, wmma::mem_row_major);
            __syncwarp();
            #pragma unroll
            for (int q = 0; q < 8; q++) {
                int idx = lane * 8 + q;
                int rr = idx >> 4, cc = idx & 15;
                int grow = row0 + wm * 32 + im * 16 + rr;
                int gcol = n0 + wn * 32 + in * 16 + cc;
                float g = patchG[w][rr][cc] + bg[e * MDIM + gcol];
                float u = patchU[w][rr][cc] + bu[e * MDIM + gcol];
                float sg = g / (1.f + expf(-g));
                g_H[grow * MDIM + gcol] = __float2half(sg * u);
            }
            __syncwarp();
        }
}

// ---------------- GEMM2: H @ W_out -> Y (fp32), 128x64 tile, BK=32 ----------------
__global__ void __launch_bounds__(256) gemm2_kernel() {
    int e = g_tile_expert[blockIdx.x];
    if (e < 0) return;
    int row0 = blockIdx.x * 128;
    int n0 = blockIdx.y * 64;

    __shared__ __half As[128][40];
    __shared__ __half Bs[32][72];

    int tid = threadIdx.x;
    int w = tid >> 5;
    int wm = w >> 1, wn = w & 1;

    const __half* Wob = g_Wo + (size_t)e * MDIM * DDIM;

    wmma::fragment<wmma::accumulator, 16, 16, 16, float> acc[2][2];
    #pragma unroll
    for (int i = 0; i < 2; i++)
        #pragma unroll
        for (int j = 0; j < 2; j++) wmma::fill_fragment(acc[i][j], 0.f);

    for (int kt = 0; kt < MDIM / 32; kt++) {
        int k0 = kt * 32;
        __syncthreads();
        #pragma unroll
        for (int v = tid; v < 512; v += 256) {
            int r = v >> 2, cseg = (v & 3) * 8;
            *reinterpret_cast<uint4*>(&As[r][cseg]) =
                *reinterpret_cast<const uint4*>(&g_H[(row0 + r) * MDIM + k0 + cseg]);
        }
        {
            int r = tid >> 3, cseg = (tid & 7) * 8;
            *reinterpret_cast<uint4*>(&Bs[r][cseg]) =
                *reinterpret_cast<const uint4*>(&Wob[(k0 + r) * DDIM + n0 + cseg]);
        }
        __syncthreads();

        #pragma unroll
        for (int kk = 0; kk < 32; kk += 16) {
            wmma::fragment<wmma::matrix_a, 16, 16, 16, __half, wmma::row_major> a[2];
            wmma::fragment<wmma::matrix_b, 16, 16, 16, __half, wmma::row_major> b[2];
            #pragma unroll
            for (int im = 0; im < 2; im++)
                wmma::load_matrix_sync(a[im], &As[wm * 32 + im * 16][kk], 40);
            #pragma unroll
            for (int in = 0; in < 2; in++)
                wmma::load_matrix_sync(b[in], &Bs[kk][wn * 32 + in * 16], 72);
            #pragma unroll
            for (int im = 0; im < 2; im++)
                #pragma unroll
                for (int in = 0; in < 2; in++)
                    wmma::mma_sync(acc[im][in], a[im], b[in], acc[im][in]);
        }
    }

    // direct fp32 store to Y
    #pragma unroll
    for (int im = 0; im < 2; im++)
        #pragma unroll
        for (int in = 0; in < 2; in++) {
            float* dst = &g_Y[(row0 + wm * 32 + im * 16) * DDIM + n0 + wn * 32 + in * 16];
            wmma::store_matrix_sync(dst, acc[im][in], DDIM, wmma::mem_row_major);
        }
}

// ---------------- combine: out[t] = w1*(Y[r1]+bo[e1]) + w2*(Y[r2]+bo[e2]) ----------------
__global__ void combine_kernel(float* __restrict__ out, const float* __restrict__ bo) {
    int t = blockIdx.x;
    int c = threadIdx.x * 4;   // 256 threads * 4 = 1024
    int e1 = g_tok_e[2 * t], e2 = g_tok_e[2 * t + 1];
    int r1 = g_offsets[e1] + g_tok_slot[2 * t];
    int r2 = g_offsets[e2] + g_tok_slot[2 * t + 1];
    float w1 = g_tok_w[2 * t], w2 = g_tok_w[2 * t + 1];
    float4 y1 = *reinterpret_cast<const float4*>(&g_Y[r1 * DDIM + c]);
    float4 y2 = *reinterpret_cast<const float4*>(&g_Y[r2 * DDIM + c]);
    float4 b1 = *reinterpret_cast<const float4*>(&bo[e1 * DDIM + c]);
    float4 b2 = *reinterpret_cast<const float4*>(&bo[e2 * DDIM + c]);
    float4 o;
    o.x = w1 * (y1.x + b1.x) + w2 * (y2.x + b2.x);
    o.y = w1 * (y1.y + b1.y) + w2 * (y2.y + b2.y);
    o.z = w1 * (y1.z + b1.z) + w2 * (y2.z + b2.z);
    o.w = w1 * (y1.w + b1.w) + w2 * (y2.w + b2.w);
    *reinterpret_cast<float4*>(&out[(size_t)t * DDIM + c]) = o;
}

// ---------------- launch ----------------
extern "C" void kernel_launch(void* const* d_in, const int* in_sizes, int n_in,
                              void* d_out, int out_size) {
    const float* residual = (const float*)d_in[0];
    const float* Wr = (const float*)d_in[1];
    const float* Wg = (const float*)d_in[2];
    const float* bg = (const float*)d_in[3];
    const float* Wu = (const float*)d_in[4];
    const float* bu = (const float*)d_in[5];
    const float* Wo = (const float*)d_in[6];
    const float* bo = (const float*)d_in[7];
    float* out = (float*)d_out;

    init_kernel<<<(ROWS_PAD + 255) / 256, 256>>>();
    convert_kernel<<<(NEXP * DDIM * MDIM / 4 + 255) / 256, 256>>>(Wg, Wu, Wo);
    router_kernel<<<T_TOKENS, 256>>>(residual, Wr);
    scan_kernel<<<1, 1>>>();
    scatter_kernel<<<(T_TOKENS * 2 + 255) / 256, 256>>>();
    gather_kernel<<<ROWS_PAD, 128>>>(residual);
    dim3 g1(MAX_TILES, MDIM / 64);
    gemm1_kernel<<<g1, 256>>>(bg, bu);
    dim3 g2(MAX_TILES, DDIM / 64);
    gemm2_kernel<<<g2, 256>>>();
    combine_kernel<<<T_TOKENS, 256>>>(out, bo);
}

// round 3
// speedup vs baseline: 1.2680x; 1.2680x over previous
#include <cuda_runtime.h>
#include <cuda_fp16.h>
#include <cstdint>

#define T_TOKENS 4096
#define DDIM 1024
#define MDIM 2048
#define NEXP 8
#define ROWS_PAD 9216      // 72 tiles * 128 rows
#define MAX_TILES 72

// ---------------- device scratch ----------------
__device__ __half g_Wg[NEXP * DDIM * MDIM];   // [E][D][M] fp16 (K-major for GEMM1)
__device__ __half g_Wu[NEXP * DDIM * MDIM];   // [E][D][M] fp16
__device__ __half g_Wo[NEXP * MDIM * DDIM];   // [E][M][D] fp16 (K-major for GEMM2)
__device__ __half g_X[ROWS_PAD * DDIM];       // gathered activations (fp16)
__device__ __half g_H[ROWS_PAD * MDIM];       // hidden = silu(g)*u (fp16)
__device__ float  g_Y[ROWS_PAD * DDIM];       // expert outputs (fp32)
__device__ int    g_counts[NEXP];
__device__ int    g_offsets[NEXP + 1];
__device__ int    g_tile_expert[MAX_TILES];
__device__ int    g_row_tok[ROWS_PAD];
__device__ int    g_tok_e[T_TOKENS * 2];
__device__ int    g_tok_slot[T_TOKENS * 2];
__device__ float  g_tok_w[T_TOKENS * 2];

// ---------------- helpers ----------------
__device__ __forceinline__ uint32_t smem_u32(const void* p) {
    uint32_t a;
    asm("{ .reg .u64 t; cvta.to.shared.u64 t, %1; cvt.u32.u64 %0, t; }" : "=r"(a) : "l"(p));
    return a;
}
__device__ __forceinline__ void cpa16(uint32_t dst, const void* src) {
    asm volatile("cp.async.cg.shared.global [%0], [%1], 16;\n" :: "r"(dst), "l"(src));
}
__device__ __forceinline__ void ldm_x4(uint32_t* r, uint32_t addr) {
    asm volatile("ldmatrix.sync.aligned.m8n8.x4.shared.b16 {%0,%1,%2,%3}, [%4];"
                 : "=r"(r[0]), "=r"(r[1]), "=r"(r[2]), "=r"(r[3]) : "r"(addr));
}
__device__ __forceinline__ void ldm_x4_t(uint32_t* r, uint32_t addr) {
    asm volatile("ldmatrix.sync.aligned.m8n8.x4.trans.shared.b16 {%0,%1,%2,%3}, [%4];"
                 : "=r"(r[0]), "=r"(r[1]), "=r"(r[2]), "=r"(r[3]) : "r"(addr));
}
__device__ __forceinline__ void mma16816(float* c, const uint32_t* a, const uint32_t* b) {
    asm volatile(
        "mma.sync.aligned.m16n8k16.row.col.f32.f16.f16.f32 "
        "{%0,%1,%2,%3}, {%4,%5,%6,%7}, {%8,%9}, {%0,%1,%2,%3};"
        : "+f"(c[0]), "+f"(c[1]), "+f"(c[2]), "+f"(c[3])
        : "r"(a[0]), "r"(a[1]), "r"(a[2]), "r"(a[3]), "r"(b[0]), "r"(b[1]));
}

// ---------------- init ----------------
__global__ void init_kernel() {
    int i = blockIdx.x * blockDim.x + threadIdx.x;
    if (i < NEXP) g_counts[i] = 0;
    if (i < ROWS_PAD) g_row_tok[i] = -1;
}

// ---------------- fp32 -> fp16 straight conversion (all three weights) ----------------
__global__ void convert_kernel(const float* __restrict__ wg,
                               const float* __restrict__ wu,
                               const float* __restrict__ wo) {
    int i = blockIdx.x * blockDim.x + threadIdx.x;   // one float4 group
    const int n4 = NEXP * DDIM * MDIM / 4;           // 4,194,304
    if (i >= n4) return;
    float4 a = reinterpret_cast<const float4*>(wg)[i];
    float4 b = reinterpret_cast<const float4*>(wu)[i];
    float4 c = reinterpret_cast<const float4*>(wo)[i];
    __half2* pg = reinterpret_cast<__half2*>(g_Wg);
    __half2* pu = reinterpret_cast<__half2*>(g_Wu);
    __half2* po = reinterpret_cast<__half2*>(g_Wo);
    pg[2 * i]     = __floats2half2_rn(a.x, a.y);
    pg[2 * i + 1] = __floats2half2_rn(a.z, a.w);
    pu[2 * i]     = __floats2half2_rn(b.x, b.y);
    pu[2 * i + 1] = __floats2half2_rn(b.z, b.w);
    po[2 * i]     = __floats2half2_rn(c.x, c.y);
    po[2 * i + 1] = __floats2half2_rn(c.z, c.w);
}

// ---------------- router ----------------
__global__ void router_kernel(const float* __restrict__ residual,
                              const float* __restrict__ Wr) {
    int t = blockIdx.x;
    __shared__ float xs[DDIM];
    __shared__ float logits[NEXP];
    int tid = threadIdx.x;   // 256 threads = 8 warps
    const float* x = residual + (size_t)t * DDIM;
    for (int i = tid; i < DDIM; i += 256) xs[i] = x[i];
    __syncthreads();
    int w = tid >> 5, lane = tid & 31;
    float s = 0.f;
    for (int i = lane; i < DDIM; i += 32) s += xs[i] * Wr[i * NEXP + w];
    #pragma unroll
    for (int o = 16; o > 0; o >>= 1) s += __shfl_xor_sync(0xffffffff, s, o);
    if (lane == 0) logits[w] = s;
    __syncthreads();
    if (tid == 0) {
        float mx = logits[0];
        #pragma unroll
        for (int e = 1; e < NEXP; e++) mx = fmaxf(mx, logits[e]);
        float p[NEXP]; float sum = 0.f;
        #pragma unroll
        for (int e = 0; e < NEXP; e++) { p[e] = expf(logits[e] - mx); sum += p[e]; }
        #pragma unroll
        for (int e = 0; e < NEXP; e++) p[e] /= sum;
        int i1 = 0;
        #pragma unroll
        for (int e = 1; e < NEXP; e++) if (p[e] > p[i1]) i1 = e;
        int i2 = -1;
        #pragma unroll
        for (int e = 0; e < NEXP; e++) {
            if (e == i1) continue;
            if (i2 < 0 || p[e] > p[i2]) i2 = e;
        }
        float w1 = p[i1], w2 = p[i2];
        float inv = 1.f / (w1 + w2 + 1e-8f);
        w1 *= inv; w2 *= inv;
        int s1 = atomicAdd(&g_counts[i1], 1);
        int s2 = atomicAdd(&g_counts[i2], 1);
        g_tok_e[2 * t] = i1;     g_tok_e[2 * t + 1] = i2;
        g_tok_slot[2 * t] = s1;  g_tok_slot[2 * t + 1] = s2;
        g_tok_w[2 * t] = w1;     g_tok_w[2 * t + 1] = w2;
    }
}

__global__ void scan_kernel() {
    int off = 0, tile = 0;
    for (int e = 0; e < NEXP; e++) {
        g_offsets[e] = off;
        int nt = (g_counts[e] + 127) / 128;
        for (int k = 0; k < nt; k++) g_tile_expert[tile++] = e;
        off += nt * 128;
    }
    g_offsets[NEXP] = off;
    for (; tile < MAX_TILES; tile++) g_tile_expert[tile] = -1;
}

__global__ void scatter_kernel() {
    int i = blockIdx.x * blockDim.x + threadIdx.x;
    if (i >= T_TOKENS * 2) return;
    int e = g_tok_e[i];
    int row = g_offsets[e] + g_tok_slot[i];
    g_row_tok[row] = i >> 1;
}

__global__ void gather_kernel(const float* __restrict__ residual) {
    int row = blockIdx.x;
    int c = threadIdx.x * 8;
    int tok = g_row_tok[row];
    __half2 h[4];
    if (tok < 0) {
        __half2 z = __half2half2(__float2half(0.f));
        h[0] = z; h[1] = z; h[2] = z; h[3] = z;
    } else {
        const float4* src = reinterpret_cast<const float4*>(residual + (size_t)tok * DDIM + c);
        float4 a = src[0], b = src[1];
        h[0] = __floats2half2_rn(a.x, a.y); h[1] = __floats2half2_rn(a.z, a.w);
        h[2] = __floats2half2_rn(b.x, b.y); h[3] = __floats2half2_rn(b.z, b.w);
    }
    *reinterpret_cast<uint4*>(g_X + row * DDIM + c) = *reinterpret_cast<uint4*>(h);
}

// ================= GEMM1: fused gate+up, 128x128, BK=32, 3-stage cp.async =================
// SMEM stage layout (halfs): A[128][40] | Bg[32][136] | Bu[32][136]
#define G1_A_H (128 * 40)
#define G1_B_H (32 * 136)
#define G1_STAGE_H (G1_A_H + 2 * G1_B_H)
#define G1_STG 3
#define G1_SMEM (G1_STG * G1_STAGE_H * 2)

__global__ void __launch_bounds__(256, 1) gemm1_kernel(const float* __restrict__ bg,
                                                       const float* __restrict__ bu) {
    int e = g_tile_expert[blockIdx.y];
    if (e < 0) return;
    int row0 = blockIdx.y * 128, n0 = blockIdx.x * 128;
    extern __shared__ __half sm[];
    uint32_t sbase = smem_u32(sm);
    int tid = threadIdx.x, lane = tid & 31, w = tid >> 5;
    int wm = w >> 2, wn = w & 3;                    // 2 x 4 warps, 64x32 each
    const __half* Wgb = g_Wg + (size_t)e * DDIM * MDIM;
    const __half* Wub = g_Wu + (size_t)e * DDIM * MDIM;

    float accG[4][4][4], accU[4][4][4];
    #pragma unroll
    for (int mt = 0; mt < 4; mt++)
        #pragma unroll
        for (int nt = 0; nt < 4; nt++)
            #pragma unroll
            for (int q = 0; q < 4; q++) { accG[mt][nt][q] = 0.f; accU[mt][nt][q] = 0.f; }

    auto load_stage = [&](int st, int kt) {
        uint32_t base = sbase + st * (G1_STAGE_H * 2);
        int k0 = kt * 32;
        #pragma unroll
        for (int i = 0; i < 2; i++) {               // A: 512 chunks of 16B
            int v = tid + i * 256;
            int r = v >> 2, c8 = (v & 3) * 8;
            cpa16(base + (r * 40 + c8) * 2, g_X + (size_t)(row0 + r) * DDIM + k0 + c8);
        }
        #pragma unroll
        for (int i = 0; i < 2; i++) {               // Bg,Bu: 512 chunks each
            int v = tid + i * 256;
            int r = v >> 4, c = (v & 15) * 8;
            cpa16(base + (G1_A_H + r * 136 + c) * 2, Wgb + (size_t)(k0 + r) * MDIM + n0 + c);
            cpa16(base + (G1_A_H + G1_B_H + r * 136 + c) * 2, Wub + (size_t)(k0 + r) * MDIM + n0 + c);
        }
        asm volatile("cp.async.commit_group;" ::: "memory");
    };

    load_stage(0, 0);
    load_stage(1, 1);

    const int KT = DDIM / 32;                       // 32
    for (int kt = 0; kt < KT; kt++) {
        asm volatile("cp.async.wait_group 1;" ::: "memory");
        __syncthreads();
        if (kt + 2 < KT) load_stage((kt + 2) % G1_STG, kt + 2);
        uint32_t base = sbase + (kt % G1_STG) * (G1_STAGE_H * 2);
        #pragma unroll
        for (int kk = 0; kk < 32; kk += 16) {
            uint32_t a[4][4];
            #pragma unroll
            for (int mt = 0; mt < 4; mt++) {
                int row = wm * 64 + mt * 16 + (lane & 15);
                int col = kk + (lane >> 4) * 8;
                ldm_x4(a[mt], base + (row * 40 + col) * 2);
            }
            uint32_t bG[2][4], bU[2][4];
            #pragma unroll
            for (int p = 0; p < 2; p++) {
                int krow = kk + (lane & 15);
                int col = wn * 32 + p * 16 + (lane >> 4) * 8;
                ldm_x4_t(bG[p], base + (G1_A_H + krow * 136 + col) * 2);
                ldm_x4_t(bU[p], base + (G1_A_H + G1_B_H + krow * 136 + col) * 2);
            }
            #pragma unroll
            for (int mt = 0; mt < 4; mt++)
                #pragma unroll
                for (int nt = 0; nt < 4; nt++) {
                    mma16816(accG[mt][nt], a[mt], &bG[nt >> 1][(nt & 1) * 2]);
                    mma16816(accU[mt][nt], a[mt], &bU[nt >> 1][(nt & 1) * 2]);
                }
        }
    }

    // epilogue: h = silu(g + bg) * (u + bu) -> fp16 H (register-only)
    const float* bgp = bg + e * MDIM + n0 + wn * 32;
    const float* bup = bu + e * MDIM + n0 + wn * 32;
    #pragma unroll
    for (int nt = 0; nt < 4; nt++) {
        int colb = nt * 8 + (lane & 3) * 2;
        float b_g0 = bgp[colb], b_g1 = bgp[colb + 1];
        float b_u0 = bup[colb], b_u1 = bup[colb + 1];
        int col = n0 + wn * 32 + colb;
        #pragma unroll
        for (int mt = 0; mt < 4; mt++) {
            int row = row0 + wm * 64 + mt * 16 + (lane >> 2);
            float g0 = accG[mt][nt][0] + b_g0, g1 = accG[mt][nt][1] + b_g1;
            float u0 = accU[mt][nt][0] + b_u0, u1 = accU[mt][nt][1] + b_u1;
            float h0 = g0 / (1.f + __expf(-g0)) * u0;
            float h1 = g1 / (1.f + __expf(-g1)) * u1;
            *reinterpret_cast<__half2*>(g_H + (size_t)row * MDIM + col) = __floats2half2_rn(h0, h1);
            float g2 = accG[mt][nt][2] + b_g0, g3 = accG[mt][nt][3] + b_g1;
            float u2 = accU[mt][nt][2] + b_u0, u3 = accU[mt][nt][3] + b_u1;
            float h2 = g2 / (1.f + __expf(-g2)) * u2;
            float h3 = g3 / (1.f + __expf(-g3)) * u3;
            *reinterpret_cast<__half2*>(g_H + (size_t)(row + 8) * MDIM + col) = __floats2half2_rn(h2, h3);
        }
    }
}

// ================= GEMM2: H @ W_out -> Y fp32, 128x128, BK=32, 3-stage =================
#define G2_STAGE_H (G1_A_H + G1_B_H)
#define G2_STG 3
#define G2_SMEM (G2_STG * G2_STAGE_H * 2)

__global__ void __launch_bounds__(256, 2) gemm2_kernel() {
    int e = g_tile_expert[blockIdx.y];
    if (e < 0) return;
    int row0 = blockIdx.y * 128, n0 = blockIdx.x * 128;
    extern __shared__ __half sm[];
    uint32_t sbase = smem_u32(sm);
    int tid = threadIdx.x, lane = tid & 31, w = tid >> 5;
    int wm = w >> 2, wn = w & 3;
    const __half* Wob = g_Wo + (size_t)e * MDIM * DDIM;

    float acc[4][4][4];
    #pragma unroll
    for (int mt = 0; mt < 4; mt++)
        #pragma unroll
        for (int nt = 0; nt < 4; nt++)
            #pragma unroll
            for (int q = 0; q < 4; q++) acc[mt][nt][q] = 0.f;

    auto load_stage = [&](int st, int kt) {
        uint32_t base = sbase + st * (G2_STAGE_H * 2);
        int k0 = kt * 32;
        #pragma unroll
        for (int i = 0; i < 2; i++) {
            int v = tid + i * 256;
            int r = v >> 2, c8 = (v & 3) * 8;
            cpa16(base + (r * 40 + c8) * 2, g_H + (size_t)(row0 + r) * MDIM + k0 + c8);
        }
        #pragma unroll
        for (int i = 0; i < 2; i++) {
            int v = tid + i * 256;
            int r = v >> 4, c = (v & 15) * 8;
            cpa16(base + (G1_A_H + r * 136 + c) * 2, Wob + (size_t)(k0 + r) * DDIM + n0 + c);
        }
        asm volatile("cp.async.commit_group;" ::: "memory");
    };

    load_stage(0, 0);
    load_stage(1, 1);

    const int KT = MDIM / 32;                        // 64
    for (int kt = 0; kt < KT; kt++) {
        asm volatile("cp.async.wait_group 1;" ::: "memory");
        __syncthreads();
        if (kt + 2 < KT) load_stage((kt + 2) % G2_STG, kt + 2);
        uint32_t base = sbase + (kt % G2_STG) * (G2_STAGE_H * 2);
        #pragma unroll
        for (int kk = 0; kk < 32; kk += 16) {
            uint32_t a[4][4];
            #pragma unroll
            for (int mt = 0; mt < 4; mt++) {
                int row = wm * 64 + mt * 16 + (lane & 15);
                int col = kk + (lane >> 4) * 8;
                ldm_x4(a[mt], base + (row * 40 + col) * 2);
            }
            uint32_t bB[2][4];
            #pragma unroll
            for (int p = 0; p < 2; p++) {
                int krow = kk + (lane & 15);
                int col = wn * 32 + p * 16 + (lane >> 4) * 8;
                ldm_x4_t(bB[p], base + (G1_A_H + krow * 136 + col) * 2);
            }
            #pragma unroll
            for (int mt = 0; mt < 4; mt++)
                #pragma unroll
                for (int nt = 0; nt < 4; nt++)
                    mma16816(acc[mt][nt], a[mt], &bB[nt >> 1][(nt & 1) * 2]);
        }
    }

    // epilogue: fp32 Y store
    #pragma unroll
    for (int nt = 0; nt < 4; nt++) {
        int colb = nt * 8 + (lane & 3) * 2;
        int col = n0 + wn * 32 + colb;
        #pragma unroll
        for (int mt = 0; mt < 4; mt++) {
            int row = row0 + wm * 64 + mt * 16 + (lane >> 2);
            float2 v0 = make_float2(acc[mt][nt][0], acc[mt][nt][1]);
            float2 v1 = make_float2(acc[mt][nt][2], acc[mt][nt][3]);
            *reinterpret_cast<float2*>(g_Y + (size_t)row * DDIM + col) = v0;
            *reinterpret_cast<float2*>(g_Y + (size_t)(row + 8) * DDIM + col) = v1;
        }
    }
}

// ---------------- combine ----------------
__global__ void combine_kernel(float* __restrict__ out, const float* __restrict__ bo) {
    int t = blockIdx.x;
    int c = threadIdx.x * 4;
    int e1 = g_tok_e[2 * t], e2 = g_tok_e[2 * t + 1];
    int r1 = g_offsets[e1] + g_tok_slot[2 * t];
    int r2 = g_offsets[e2] + g_tok_slot[2 * t + 1];
    float w1 = g_tok_w[2 * t], w2 = g_tok_w[2 * t + 1];
    float4 y1 = *reinterpret_cast<const float4*>(&g_Y[(size_t)r1 * DDIM + c]);
    float4 y2 = *reinterpret_cast<const float4*>(&g_Y[(size_t)r2 * DDIM + c]);
    float4 b1 = *reinterpret_cast<const float4*>(&bo[e1 * DDIM + c]);
    float4 b2 = *reinterpret_cast<const float4*>(&bo[e2 * DDIM + c]);
    float4 o;
    o.x = w1 * (y1.x + b1.x) + w2 * (y2.x + b2.x);
    o.y = w1 * (y1.y + b1.y) + w2 * (y2.y + b2.y);
    o.z = w1 * (y1.z + b1.z) + w2 * (y2.z + b2.z);
    o.w = w1 * (y1.w + b1.w) + w2 * (y2.w + b2.w);
    *reinterpret_cast<float4*>(&out[(size_t)t * DDIM + c]) = o;
}

// ---------------- launch ----------------
extern "C" void kernel_launch(void* const* d_in, const int* in_sizes, int n_in,
                              void* d_out, int out_size) {
    const float* residual = (const float*)d_in[0];
    const float* Wr = (const float*)d_in[1];
    const float* Wg = (const float*)d_in[2];
    const float* bg = (const float*)d_in[3];
    const float* Wu = (const float*)d_in[4];
    const float* bu = (const float*)d_in[5];
    const float* Wo = (const float*)d_in[6];
    const float* bo = (const float*)d_in[7];
    float* out = (float*)d_out;

    static bool attr_set = false;
    if (!attr_set) {
        cudaFuncSetAttribute(gemm1_kernel, cudaFuncAttributeMaxDynamicSharedMemorySize, G1_SMEM);
        cudaFuncSetAttribute(gemm2_kernel, cudaFuncAttributeMaxDynamicSharedMemorySize, G2_SMEM);
        attr_set = true;
    }

    init_kernel<<<(ROWS_PAD + 255) / 256, 256>>>();
    convert_kernel<<<(NEXP * DDIM * MDIM / 4 + 255) / 256, 256>>>(Wg, Wu, Wo);
    router_kernel<<<T_TOKENS, 256>>>(residual, Wr);
    scan_kernel<<<1, 1>>>();
    scatter_kernel<<<(T_TOKENS * 2 + 255) / 256, 256>>>();
    gather_kernel<<<ROWS_PAD, 128>>>(residual);
    dim3 g1(MDIM / 128, MAX_TILES);     // n-major for L2 reuse of A rows
    gemm1_kernel<<<g1, 256, G1_SMEM>>>(bg, bu);
    dim3 g2(DDIM / 128, MAX_TILES);
    gemm2_kernel<<<g2, 256, G2_SMEM>>>();
    combine_kernel<<<T_TOKENS, 256>>>(out, bo);
}

// round 5
// speedup vs baseline: 1.5235x; 1.2015x over previous
#include <cuda_runtime.h>
#include <cuda_fp16.h>
#include <cstdint>

#define T_TOKENS 4096
#define DDIM 1024
#define MDIM 2048
#define NEXP 8
#define ROWS_PAD 9216      // 72 tiles * 128 rows
#define MAX_TILES 72

// Block layout: all GEMM operands stored as 16KB blocks of (64 k) x (128 n/m),
// element (k, j) at byte  k-major-A: m*128 + ((k*2) ^ ((m&7)<<4))   [A blocks: 128 m x 64 k]
//                        B blocks:   k*256 + ((n*2) ^ ((k&7)<<4))   [64 k x 128 n]
// g_X : [72 rowtiles][16 kt] A-blocks
// g_H : [72 rowtiles][32 kt] A-blocks
// g_Wg/g_Wu: [E][16 nt][16 kt] B-blocks ; g_Wo: [E][8 nt][32 kt] B-blocks
__device__ __half g_Wg[NEXP * DDIM * MDIM];
__device__ __half g_Wu[NEXP * DDIM * MDIM];
__device__ __half g_Wo[NEXP * MDIM * DDIM];
__device__ __half g_X[ROWS_PAD * DDIM];
__device__ __half g_H[ROWS_PAD * MDIM];
__device__ float  g_Y[ROWS_PAD * DDIM];
__device__ int    g_counts[NEXP];
__device__ int    g_offsets[NEXP + 1];
__device__ int    g_tile_expert[MAX_TILES];
__device__ int    g_row_tok[ROWS_PAD];
__device__ int    g_tok_e[T_TOKENS * 2];
__device__ int    g_tok_slot[T_TOKENS * 2];
__device__ float  g_tok_w[T_TOKENS * 2];

// ---------------- helpers ----------------
__device__ __forceinline__ uint32_t smem_u32(const void* p) {
    uint32_t a;
    asm("{ .reg .u64 t; cvta.to.shared.u64 t, %1; cvt.u32.u64 %0, t; }" : "=r"(a) : "l"(p));
    return a;
}
__device__ __forceinline__ void mbar_init(uint32_t a, uint32_t cnt) {
    asm volatile("mbarrier.init.shared.b64 [%0], %1;" :: "r"(a), "r"(cnt) : "memory");
}
__device__ __forceinline__ void mbar_expect_tx(uint32_t a, uint32_t bytes) {
    asm volatile("mbarrier.arrive.expect_tx.shared.b64 _, [%0], %1;" :: "r"(a), "r"(bytes) : "memory");
}
__device__ __forceinline__ void bulk_g2s(uint32_t dst, const void* src, uint32_t bytes, uint32_t mbar) {
    asm volatile("cp.async.bulk.shared::cta.global.mbarrier::complete_tx::bytes [%0], [%1], %2, [%3];"
                 :: "r"(dst), "l"(src), "r"(bytes), "r"(mbar) : "memory");
}
__device__ __forceinline__ void mbar_wait(uint32_t a, uint32_t parity) {
    asm volatile(
        "{\n\t.reg .pred P1;\n\t"
        "W%=:\n\t"
        "mbarrier.try_wait.parity.acquire.cta.shared::cta.b64 P1, [%0], %1, 0x989680;\n\t"
        "@P1 bra.uni D%=;\n\t"
        "bra.uni W%=;\n\t"
        "D%=:\n\t}"
        :: "r"(a), "r"(parity) : "memory");
}
#define FENCE_ASYNC() asm volatile("fence.proxy.async.shared::cta;" ::: "memory")
__device__ __forceinline__ void ldm_x4(uint32_t* r, uint32_t addr) {
    asm volatile("ldmatrix.sync.aligned.m8n8.x4.shared.b16 {%0,%1,%2,%3}, [%4];"
                 : "=r"(r[0]), "=r"(r[1]), "=r"(r[2]), "=r"(r[3]) : "r"(addr));
}
__device__ __forceinline__ void ldm_x4_t(uint32_t* r, uint32_t addr) {
    asm volatile("ldmatrix.sync.aligned.m8n8.x4.trans.shared.b16 {%0,%1,%2,%3}, [%4];"
                 : "=r"(r[0]), "=r"(r[1]), "=r"(r[2]), "=r"(r[3]) : "r"(addr));
}
__device__ __forceinline__ void mma16816(float* c, const uint32_t* a, const uint32_t* b) {
    asm volatile(
        "mma.sync.aligned.m16n8k16.row.col.f32.f16.f16.f32 "
        "{%0,%1,%2,%3}, {%4,%5,%6,%7}, {%8,%9}, {%0,%1,%2,%3};"
        : "+f"(c[0]), "+f"(c[1]), "+f"(c[2]), "+f"(c[3])
        : "r"(a[0]), "r"(a[1]), "r"(a[2]), "r"(a[3]), "r"(b[0]), "r"(b[1]));
}

// ---------------- init ----------------
__global__ void init_kernel() {
    int i = blockIdx.x * blockDim.x + threadIdx.x;
    if (i < NEXP) g_counts[i] = 0;
    if (i < ROWS_PAD) g_row_tok[i] = -1;
}

// ---------------- convert: fp32 [E][K][N] -> tiled+swizzled fp16 B-blocks ----------------
// y=0: W_gate->g_Wg (K=1024,N=2048); y=1: W_up->g_Wu; y=2: W_out->g_Wo (K=2048,N=1024)
__global__ void convert_kernel(const float* __restrict__ wg,
                               const float* __restrict__ wu,
                               const float* __restrict__ wo) {
    __shared__ float tile[64][128];
    const float* src;
    __half* dst;
    int KD, ND;
    if (blockIdx.y == 0)      { src = wg; dst = g_Wg; KD = DDIM; ND = MDIM; }
    else if (blockIdx.y == 1) { src = wu; dst = g_Wu; KD = DDIM; ND = MDIM; }
    else                      { src = wo; dst = g_Wo; KD = MDIM; ND = DDIM; }
    int NT = ND / 128, KT = KD / 64;
    int x = blockIdx.x;                 // e*NT*KT + nt*KT + kt   (2048 for all)
    int e = x / (NT * KT);
    int nt = (x / KT) % NT;
    int kt = x % KT;
    int k0 = kt * 64, n0 = nt * 128;
    int tid = threadIdx.x;              // 256
    const float* s = src + (size_t)e * KD * ND;
    #pragma unroll
    for (int i = 0; i < 32; i++) {
        int idx = tid + i * 256;        // 8192
        int k = idx >> 7, n = idx & 127;
        tile[k][n] = s[(size_t)(k0 + k) * ND + n0 + n];
    }
    __syncthreads();
    uint4* out = reinterpret_cast<uint4*>(dst + (size_t)x * 8192);
    #pragma unroll
    for (int i = 0; i < 4; i++) {
        int idx = tid + i * 256;        // 1024 uint4
        int b16 = idx * 16;
        int k = b16 >> 8;
        int n = ((b16 & 255) ^ ((k & 7) << 4)) >> 1;
        __half2 h[4];
        #pragma unroll
        for (int q = 0; q < 4; q++)
            h[q] = __floats2half2_rn(tile[k][n + 2 * q], tile[k][n + 2 * q + 1]);
        out[idx] = *reinterpret_cast<uint4*>(h);
    }
}

// ---------------- router ----------------
__global__ void router_kernel(const float* __restrict__ residual,
                              const float* __restrict__ Wr) {
    int t = blockIdx.x;
    __shared__ float xs[DDIM];
    __shared__ float logits[NEXP];
    int tid = threadIdx.x;
    const float* x = residual + (size_t)t * DDIM;
    for (int i = tid; i < DDIM; i += 256) xs[i] = x[i];
    __syncthreads();
    int w = tid >> 5, lane = tid & 31;
    float s = 0.f;
    for (int i = lane; i < DDIM; i += 32) s += xs[i] * Wr[i * NEXP + w];
    #pragma unroll
    for (int o = 16; o > 0; o >>= 1) s += __shfl_xor_sync(0xffffffff, s, o);
    if (lane == 0) logits[w] = s;
    __syncthreads();
    if (tid == 0) {
        float mx = logits[0];
        #pragma unroll
        for (int e = 1; e < NEXP; e++) mx = fmaxf(mx, logits[e]);
        float p[NEXP]; float sum = 0.f;
        #pragma unroll
        for (int e = 0; e < NEXP; e++) { p[e] = expf(logits[e] - mx); sum += p[e]; }
        #pragma unroll
        for (int e = 0; e < NEXP; e++) p[e] /= sum;
        int i1 = 0;
        #pragma unroll
        for (int e = 1; e < NEXP; e++) if (p[e] > p[i1]) i1 = e;
        int i2 = -1;
        #pragma unroll
        for (int e = 0; e < NEXP; e++) {
            if (e == i1) continue;
            if (i2 < 0 || p[e] > p[i2]) i2 = e;
        }
        float w1 = p[i1], w2 = p[i2];
        float inv = 1.f / (w1 + w2 + 1e-8f);
        w1 *= inv; w2 *= inv;
        int s1 = atomicAdd(&g_counts[i1], 1);
        int s2 = atomicAdd(&g_counts[i2], 1);
        g_tok_e[2 * t] = i1;     g_tok_e[2 * t + 1] = i2;
        g_tok_slot[2 * t] = s1;  g_tok_slot[2 * t + 1] = s2;
        g_tok_w[2 * t] = w1;     g_tok_w[2 * t + 1] = w2;
    }
}

__global__ void scan_kernel() {
    int off = 0, tile = 0;
    for (int e = 0; e < NEXP; e++) {
        g_offsets[e] = off;
        int nt = (g_counts[e] + 127) / 128;
        for (int k = 0; k < nt; k++) g_tile_expert[tile++] = e;
        off += nt * 128;
    }
    g_offsets[NEXP] = off;
    for (; tile < MAX_TILES; tile++) g_tile_expert[tile] = -1;
}

__global__ void scatter_kernel() {
    int i = blockIdx.x * blockDim.x + threadIdx.x;
    if (i >= T_TOKENS * 2) return;
    int e = g_tok_e[i];
    int row = g_offsets[e] + g_tok_slot[i];
    g_row_tok[row] = i >> 1;
}

// gather -> A-block layout (zero pads)
__global__ void gather_kernel(const float* __restrict__ residual) {
    int row = blockIdx.x;
    int c = threadIdx.x * 8;            // 128 threads, 8 cols each
    int tok = g_row_tok[row];
    __half2 h[4];
    if (tok < 0) {
        __half2 z = __half2half2(__float2half(0.f));
        h[0] = z; h[1] = z; h[2] = z; h[3] = z;
    } else {
        const float4* src = reinterpret_cast<const float4*>(residual + (size_t)tok * DDIM + c);
        float4 a = src[0], b = src[1];
        h[0] = __floats2half2_rn(a.x, a.y); h[1] = __floats2half2_rn(a.z, a.w);
        h[2] = __floats2half2_rn(b.x, b.y); h[3] = __floats2half2_rn(b.z, b.w);
    }
    int rt = row >> 7, m = row & 127;
    int kt = c >> 6, k = c & 63;
    // uint4 index within block: m*8 + ((k>>3) ^ (m&7))
    reinterpret_cast<uint4*>(g_X)[(size_t)(rt * 16 + kt) * 1024 + m * 8 + ((k >> 3) ^ (m & 7))] =
        *reinterpret_cast<uint4*>(h);
}

// ================= GEMM1: fused gate+up, 128x128, BK=64, bulk-copy pipeline =================
#define G1_STG 3
#define G1_NC 16
#define G1_STAGE_B 49152
#define G1_SMEM (1024 + G1_STG * G1_STAGE_B)

__global__ void __launch_bounds__(256) gemm1_kernel(const float* __restrict__ bg,
                                                    const float* __restrict__ bu) {
    int e = g_tile_expert[blockIdx.y];
    if (e < 0) return;
    int rt = blockIdx.y, nt_ = blockIdx.x;
    int row0 = rt * 128, n0 = nt_ * 128;
    extern __shared__ char smc[];
    uint32_t sb = smem_u32(smc);
    int tid = threadIdx.x, lane = tid & 31, w = tid >> 5;
    int wm = w >> 2, wn = w & 3;        // 2x4 warps, 64x32 each

    const char* Ablk  = (const char*)g_X  + (size_t)(rt * 16) * 16384;
    const char* Bgblk = (const char*)g_Wg + (size_t)((e * 16 + nt_) * 16) * 16384;
    const char* Bublk = (const char*)g_Wu + (size_t)((e * 16 + nt_) * 16) * 16384;

    if (tid == 0) {
        #pragma unroll
        for (int s = 0; s < G1_STG; s++) mbar_init(sb + 8 * s, 1);
    }
    __syncthreads();
    FENCE_ASYNC();

    auto issue = [&](int c) {
        int b = c % G1_STG;
        uint32_t mb = sb + 8 * b;
        uint32_t dst = sb + 1024 + b * G1_STAGE_B;
        mbar_expect_tx(mb, G1_STAGE_B);
        bulk_g2s(dst,          Ablk  + (size_t)c * 16384, 16384, mb);
        bulk_g2s(dst + 16384,  Bgblk + (size_t)c * 16384, 16384, mb);
        bulk_g2s(dst + 32768,  Bublk + (size_t)c * 16384, 16384, mb);
    };
    if (tid == 0) { issue(0); issue(1); issue(2); }

    float accG[4][4][4], accU[4][4][4];
    #pragma unroll
    for (int mt = 0; mt < 4; mt++)
        #pragma unroll
        for (int nt = 0; nt < 4; nt++)
            #pragma unroll
            for (int q = 0; q < 4; q++) { accG[mt][nt][q] = 0.f; accU[mt][nt][q] = 0.f; }

    for (int c = 0; c < G1_NC; c++) {
        mbar_wait(sb + 8 * (c % G1_STG), (c / G1_STG) & 1);
        uint32_t Ab = sb + 1024 + (c % G1_STG) * G1_STAGE_B;
        uint32_t Bgb = Ab + 16384, Bub = Ab + 32768;
        #pragma unroll
        for (int kk = 0; kk < 64; kk += 16) {
            uint32_t a[4][4];
            #pragma unroll
            for (int mt = 0; mt < 4; mt++) {
                int m = wm * 64 + mt * 16 + (lane & 15);
                int colk = kk + (lane >> 4) * 8;
                ldm_x4(a[mt], Ab + m * 128 + ((colk * 2) ^ ((m & 7) << 4)));
            }
            uint32_t bG[2][4], bU[2][4];
            #pragma unroll
            for (int p = 0; p < 2; p++) {
                int krow = kk + (lane & 15);
                int coln = wn * 32 + p * 16 + (lane >> 4) * 8;
                uint32_t off = krow * 256 + ((coln * 2) ^ ((krow & 7) << 4));
                ldm_x4_t(bG[p], Bgb + off);
                ldm_x4_t(bU[p], Bub + off);
            }
            #pragma unroll
            for (int mt = 0; mt < 4; mt++)
                #pragma unroll
                for (int nt = 0; nt < 4; nt++) {
                    mma16816(accG[mt][nt], a[mt], &bG[nt >> 1][(nt & 1) * 2]);
                    mma16816(accU[mt][nt], a[mt], &bU[nt >> 1][(nt & 1) * 2]);
                }
        }
        __syncthreads();
        if (tid == 0 && c + G1_STG < G1_NC) issue(c + G1_STG);
    }

    // epilogue: h = silu(g+bg)*(u+bu) -> fp16 H in A-block layout
    const float* bgp = bg + e * MDIM + n0 + wn * 32;
    const float* bup = bu + e * MDIM + n0 + wn * 32;
    #pragma unroll
    for (int nt = 0; nt < 4; nt++) {
        int colb = nt * 8 + (lane & 3) * 2;
        float b_g0 = bgp[colb], b_g1 = bgp[colb + 1];
        float b_u0 = bup[colb], b_u1 = bup[colb + 1];
        int col = n0 + wn * 32 + colb;          // global H column
        int kt = col >> 6, k2 = (col & 63) * 2;
        size_t blk = (size_t)(rt * 32 + kt) * 16384;
        #pragma unroll
        for (int mt = 0; mt < 4; mt++) {
            int m = wm * 64 + mt * 16 + (lane >> 2);
            float g0 = accG[mt][nt][0] + b_g0, g1 = accG[mt][nt][1] + b_g1;
            float u0 = accU[mt][nt][0] + b_u0, u1 = accU[mt][nt][1] + b_u1;
            float h0 = g0 / (1.f + __expf(-g0)) * u0;
            float h1 = g1 / (1.f + __expf(-g1)) * u1;
            *reinterpret_cast<__half2*>((char*)g_H + blk + m * 128 + (k2 ^ ((m & 7) << 4))) =
                __floats2half2_rn(h0, h1);
            int m2 = m + 8;
            float g2 = accG[mt][nt][2] + b_g0, g3 = accG[mt][nt][3] + b_g1;
            float u2 = accU[mt][nt][2] + b_u0, u3 = accU[mt][nt][3] + b_u1;
            float h2 = g2 / (1.f + __expf(-g2)) * u2;
            float h3 = g3 / (1.f + __expf(-g3)) * u3;
            *reinterpret_cast<__half2*>((char*)g_H + blk + m2 * 128 + (k2 ^ ((m2 & 7) << 4))) =
                __floats2half2_rn(h2, h3);
        }
    }
}

// ================= GEMM2: H @ W_out -> Y fp32, 128x128, BK=64, bulk pipeline =================
#define G2_STG 4
#define G2_NC 32
#define G2_STAGE_B 32768
#define G2_SMEM (1024 + G2_STG * G2_STAGE_B)

__global__ void __launch_bounds__(256) gemm2_kernel() {
    int e = g_tile_expert[blockIdx.y];
    if (e < 0) return;
    int rt = blockIdx.y, nt_ = blockIdx.x;
    int row0 = rt * 128, n0 = nt_ * 128;
    extern __shared__ char smc[];
    uint32_t sb = smem_u32(smc);
    int tid = threadIdx.x, lane = tid & 31, w = tid >> 5;
    int wm = w >> 2, wn = w & 3;

    const char* Ablk = (const char*)g_H  + (size_t)(rt * 32) * 16384;
    const char* Bblk = (const char*)g_Wo + (size_t)((e * 8 + nt_) * 32) * 16384;

    if (tid == 0) {
        #pragma unroll
        for (int s = 0; s < G2_STG; s++) mbar_init(sb + 8 * s, 1);
    }
    __syncthreads();
    FENCE_ASYNC();

    auto issue = [&](int c) {
        int b = c % G2_STG;
        uint32_t mb = sb + 8 * b;
        uint32_t dst = sb + 1024 + b * G2_STAGE_B;
        mbar_expect_tx(mb, G2_STAGE_B);
        bulk_g2s(dst,         Ablk + (size_t)c * 16384, 16384, mb);
        bulk_g2s(dst + 16384, Bblk + (size_t)c * 16384, 16384, mb);
    };
    if (tid == 0) { issue(0); issue(1); issue(2); issue(3); }

    float acc[4][4][4];
    #pragma unroll
    for (int mt = 0; mt < 4; mt++)
        #pragma unroll
        for (int nt = 0; nt < 4; nt++)
            #pragma unroll
            for (int q = 0; q < 4; q++) acc[mt][nt][q] = 0.f;

    for (int c = 0; c < G2_NC; c++) {
        mbar_wait(sb + 8 * (c % G2_STG), (c / G2_STG) & 1);
        uint32_t Ab = sb + 1024 + (c % G2_STG) * G2_STAGE_B;
        uint32_t Bb = Ab + 16384;
        #pragma unroll
        for (int kk = 0; kk < 64; kk += 16) {
            uint32_t a[4][4];
            #pragma unroll
            for (int mt = 0; mt < 4; mt++) {
                int m = wm * 64 + mt * 16 + (lane & 15);
                int colk = kk + (lane >> 4) * 8;
                ldm_x4(a[mt], Ab + m * 128 + ((colk * 2) ^ ((m & 7) << 4)));
            }
            uint32_t bB[2][4];
            #pragma unroll
            for (int p = 0; p < 2; p++) {
                int krow = kk + (lane & 15);
                int coln = wn * 32 + p * 16 + (lane >> 4) * 8;
                ldm_x4_t(bB[p], Bb + krow * 256 + ((coln * 2) ^ ((krow & 7) << 4)));
            }
            #pragma unroll
            for (int mt = 0; mt < 4; mt++)
                #pragma unroll
                for (int nt = 0; nt < 4; nt++)
                    mma16816(acc[mt][nt], a[mt], &bB[nt >> 1][(nt & 1) * 2]);
        }
        __syncthreads();
        if (tid == 0 && c + G2_STG < G2_NC) issue(c + G2_STG);
    }

    // epilogue: fp32 Y store (linear)
    #pragma unroll
    for (int nt = 0; nt < 4; nt++) {
        int colb = nt * 8 + (lane & 3) * 2;
        int col = n0 + wn * 32 + colb;
        #pragma unroll
        for (int mt = 0; mt < 4; mt++) {
            int row = row0 + wm * 64 + mt * 16 + (lane >> 2);
            float2 v0 = make_float2(acc[mt][nt][0], acc[mt][nt][1]);
            float2 v1 = make_float2(acc[mt][nt][2], acc[mt][nt][3]);
            *reinterpret_cast<float2*>(g_Y + (size_t)row * DDIM + col) = v0;
            *reinterpret_cast<float2*>(g_Y + (size_t)(row + 8) * DDIM + col) = v1;
        }
    }
}

// ---------------- combine ----------------
__global__ void combine_kernel(float* __restrict__ out, const float* __restrict__ bo) {
    int t = blockIdx.x;
    int c = threadIdx.x * 4;
    int e1 = g_tok_e[2 * t], e2 = g_tok_e[2 * t + 1];
    int r1 = g_offsets[e1] + g_tok_slot[2 * t];
    int r2 = g_offsets[e2] + g_tok_slot[2 * t + 1];
    float w1 = g_tok_w[2 * t], w2 = g_tok_w[2 * t + 1];
    float4 y1 = *reinterpret_cast<const float4*>(&g_Y[(size_t)r1 * DDIM + c]);
    float4 y2 = *reinterpret_cast<const float4*>(&g_Y[(size_t)r2 * DDIM + c]);
    float4 b1 = *reinterpret_cast<const float4*>(&bo[e1 * DDIM + c]);
    float4 b2 = *reinterpret_cast<const float4*>(&bo[e2 * DDIM + c]);
    float4 o;
    o.x = w1 * (y1.x + b1.x) + w2 * (y2.x + b2.x);
    o.y = w1 * (y1.y + b1.y) + w2 * (y2.y + b2.y);
    o.z = w1 * (y1.z + b1.z) + w2 * (y2.z + b2.z);
    o.w = w1 * (y1.w + b1.w) + w2 * (y2.w + b2.w);
    *reinterpret_cast<float4*>(&out[(size_t)t * DDIM + c]) = o;
}

// ---------------- launch ----------------
extern "C" void kernel_launch(void* const* d_in, const int* in_sizes, int n_in,
                              void* d_out, int out_size) {
    const float* residual = (const float*)d_in[0];
    const float* Wr = (const float*)d_in[1];
    const float* Wg = (const float*)d_in[2];
    const float* bg = (const float*)d_in[3];
    const float* Wu = (const float*)d_in[4];
    const float* bu = (const float*)d_in[5];
    const float* Wo = (const float*)d_in[6];
    const float* bo = (const float*)d_in[7];
    float* out = (float*)d_out;

    static bool attr_set = false;
    if (!attr_set) {
        cudaFuncSetAttribute(gemm1_kernel, cudaFuncAttributeMaxDynamicSharedMemorySize, G1_SMEM);
        cudaFuncSetAttribute(gemm2_kernel, cudaFuncAttributeMaxDynamicSharedMemorySize, G2_SMEM);
        attr_set = true;
    }

    init_kernel<<<(ROWS_PAD + 255) / 256, 256>>>();
    dim3 cg(2048, 3);
    convert_kernel<<<cg, 256>>>(Wg, Wu, Wo);
    router_kernel<<<T_TOKENS, 256>>>(residual, Wr);
    scan_kernel<<<1, 1>>>();
    scatter_kernel<<<(T_TOKENS * 2 + 255) / 256, 256>>>();
    gather_kernel<<<ROWS_PAD, 128>>>(residual);
    dim3 g1(MDIM / 128, MAX_TILES);
    gemm1_kernel<<<g1, 256, G1_SMEM>>>(bg, bu);
    dim3 g2(DDIM / 128, MAX_TILES);
    gemm2_kernel<<<g2, 256, G2_SMEM>>>();
    combine_kernel<<<T_TOKENS, 256>>>(out, bo);
}